// round 5
// baseline (speedup 1.0000x reference)
#include <cuda_runtime.h>
#include <math.h>

#define NN   2048
#define CC   64
#define NT   256           // j-threads per block
#define ICH  16            // i rows per block
#define GX   (NN / NT)     // 8
#define GY   (NN / ICH)    // 128
#define NBLK (GX * GY)     // 1024
#define NBUCK 64
#define NWORK GX           // 8 worker blocks (blockIdx.y == 0)
#define L2E  1.4426950408889634f

// ---- device scratch (zero-init at load; counters reset by last block) ----
__device__ float4   g_pos[NN];      // x, y, z, s0
__device__ float4   g_exp[NN];      // exp(-r_lo), exp(-d_lo), exp(-r_hi), exp(-d_hi)
__device__ float    g_w0[NN];
__device__ double   g_accs[NBUCK];
__device__ unsigned g_count;
__device__ unsigned g_ready;

__device__ __forceinline__ float sqrt_approx(float x) {
    float r; asm("sqrt.approx.f32 %0, %1;" : "=f"(r) : "f"(x)); return r;
}
__device__ __forceinline__ float rcp_approx(float x) {
    float r; asm("rcp.approx.f32 %0, %1;" : "=f"(r) : "f"(x)); return r;
}
__device__ __forceinline__ float ex2_approx(float x) {
    float r; asm("ex2.approx.f32 %0, %1;" : "=f"(r) : "f"(x)); return r;
}

__global__ void __launch_bounds__(NT, 7) fused_kernel(
    const float* __restrict__ X,     // (N,3)
    const float* __restrict__ embs,  // (N,C)
    const float* __restrict__ w0,
    const float* __restrict__ s0,
    const float* __restrict__ mask,  // (N,N)
    const float* __restrict__ df,    // (2C,)
    const float* __restrict__ rf,    // (2C,)
    float* __restrict__ out)
{
    const int tid = threadIdx.x;
    const int j   = blockIdx.x * NT + tid;
    const int i0  = blockIdx.y * ICH;

    __shared__ float4 sPosI[ICH];    // x, y, z, s0
    __shared__ float4 sMiscI[ICH];   // w0, exp(-r_hi), exp(-d_hi), pad
    __shared__ float  sred[NT];

    // ---- phase 0 (worker blocks only): per-node precompute, once per node ----
    if (blockIdx.y == 0) {
        const int n = j;   // 8 blocks x 256 threads cover all 2048 nodes
        const float4* e = (const float4*)(embs + (size_t)n * CC);
        float rl = 0.f, rh = 0.f, dl = 0.f, dh = 0.f;
#pragma unroll 4
        for (int c = 0; c < CC / 4; c++) {
            const float4 v = e[c];
            rl = fmaf(v.x, __ldg(rf + 4*c + 0), rl);
            rl = fmaf(v.y, __ldg(rf + 4*c + 1), rl);
            rl = fmaf(v.z, __ldg(rf + 4*c + 2), rl);
            rl = fmaf(v.w, __ldg(rf + 4*c + 3), rl);
            rh = fmaf(v.x, __ldg(rf + CC + 4*c + 0), rh);
            rh = fmaf(v.y, __ldg(rf + CC + 4*c + 1), rh);
            rh = fmaf(v.z, __ldg(rf + CC + 4*c + 2), rh);
            rh = fmaf(v.w, __ldg(rf + CC + 4*c + 3), rh);
            dl = fmaf(v.x, __ldg(df + 4*c + 0), dl);
            dl = fmaf(v.y, __ldg(df + 4*c + 1), dl);
            dl = fmaf(v.z, __ldg(df + 4*c + 2), dl);
            dl = fmaf(v.w, __ldg(df + 4*c + 3), dl);
            dh = fmaf(v.x, __ldg(df + CC + 4*c + 0), dh);
            dh = fmaf(v.y, __ldg(df + CC + 4*c + 1), dh);
            dh = fmaf(v.z, __ldg(df + CC + 4*c + 2), dh);
            dh = fmaf(v.w, __ldg(df + CC + 4*c + 3), dh);
        }
        g_pos[n] = make_float4(X[3*n], X[3*n+1], X[3*n+2], s0[n]);
        g_exp[n] = make_float4(ex2_approx(-L2E * rl), ex2_approx(-L2E * dl),
                               ex2_approx(-L2E * rh), ex2_approx(-L2E * dh));
        g_w0[n]  = w0[n];
        __threadfence();
        __syncthreads();
        if (tid == 0) atomicAdd(&g_ready, 1u);
    }

    // ---- prefetch first mask group (independent of node data) ----
    float mk[8], mk2[8];
#pragma unroll
    for (int k = 0; k < 8; k++)
        mk[k] = __ldg(mask + (size_t)(i0 + k) * NN + j);

    // ---- wait for all 8 worker blocks ----
    if (tid == 0) {
        volatile unsigned* vr = &g_ready;
        while (*vr < NWORK) __nanosleep(64);
    }
    __syncthreads();
    __threadfence();

    // ---- stage i-side node data into shared ----
    if (tid < ICH) {
        sPosI[tid] = g_pos[i0 + tid];
    } else if (tid >= 32 && tid < 32 + ICH) {
        const int i = i0 + (tid - 32);
        const float4 e = g_exp[i];
        sMiscI[tid - 32] = make_float4(g_w0[i], e.z, e.w, 0.f);
    }

    // j-side node data
    const float4 pj  = g_pos[j];   // xj, yj, zj, s0j
    const float4 ej  = g_exp[j];   // eRlo, eDlo, -, -
    const float  w0j = g_w0[j];
    __syncthreads();

    // ---- pairwise energy ----
    float acc = 0.f;
#pragma unroll
    for (int g = 0; g < ICH / 8; g++) {
        if (g + 1 < ICH / 8) {
#pragma unroll
            for (int k = 0; k < 8; k++)
                mk2[k] = __ldg(mask + (size_t)(i0 + (g + 1) * 8 + k) * NN + j);
        }
#pragma unroll
        for (int k = 0; k < 8; k++) {
            const int kk = g * 8 + k;
            const float4 pi = sPosI[kk];
            const float4 mi = sMiscI[kk];

            const float dx = pj.x - pi.x;
            const float dy = pj.y - pi.y;
            const float dz = pj.z - pi.z;
            const float r2 = fmaf(dx, dx, fmaf(dy, dy, fmaf(dz, dz, 3e-6f)));
            const float D  = sqrt_approx(r2);

            // sigmoid(a_i + b_j) = 1 / (1 + exp(-a_i) * exp(-b_j))
            const float sr = rcp_approx(fmaf(mi.y, ej.x, 1.f));
            const float sd = rcp_approx(fmaf(mi.z, ej.y, 1.f));

            const float s  = (pi.w + pj.w) * fmaf(0.8f, sr, 0.4f);
            const float Dm = D - s;

            // attr*3 = t*u + t^3 + t^10, t = exp(-Dm^2), u = exp(0.6 Dm - 0.09)
            const float t   = ex2_approx(-L2E * Dm * Dm);
            const float u   = ex2_approx(fmaf(0.6f * L2E, Dm, -0.09f * L2E));
            const float t2  = t * t;
            const float t3  = t2 * t;
            const float t4  = t2 * t2;
            const float t8  = t4 * t4;
            const float t10 = t8 * t2;
            const float attr3 = fmaf(t, u, t3 + t10);

            const float w = sqrt_approx(fmaf(mi.x, w0j, 1e-6f)) * (sd + 0.5f);

            // repl = 5 * exp(-0.3 * D^3), D^3 = D * r2
            const float repl = 5.f * ex2_approx((-0.3f * L2E) * D * r2);

            acc += mk[k] * fmaf(-w * (1.f / 3.f), attr3, repl);
        }
#pragma unroll
        for (int k = 0; k < 8; k++) mk[k] = mk2[k];
    }

    // ---- block reduction ----
    sred[tid] = acc;
    __syncthreads();
#pragma unroll
    for (int off = NT / 2; off >= 32; off >>= 1) {
        if (tid < off) sred[tid] += sred[tid + off];
        __syncthreads();
    }
    if (tid < 32) {
        float v = sred[tid];
#pragma unroll
        for (int off = 16; off > 0; off >>= 1)
            v += __shfl_down_sync(0xFFFFFFFFu, v, off);

        if (tid == 0) {
            const int bucket = (blockIdx.y * GX + blockIdx.x) & (NBUCK - 1);
            atomicAdd(&g_accs[bucket], (double)v);
            __threadfence();
            const unsigned prev = atomicAdd(&g_count, 1u);
            if (prev == NBLK - 1) {
                __threadfence();
                double total = 0.0;
#pragma unroll
                for (int b = 0; b < NBUCK; b++) {
                    total += g_accs[b];
                    g_accs[b] = 0.0;     // reset for next graph replay
                }
                const float r = (float)total;
                out[0] = isnan(r) ? 1e-6f : r;
                g_ready = 0u;
                g_count = 0u;
            }
        }
    }
}

extern "C" void kernel_launch(void* const* d_in, const int* in_sizes, int n_in,
                              void* d_out, int out_size) {
    const float* X    = (const float*)d_in[0];  // (1, N, 3)
    const float* embs = (const float*)d_in[1];  // (1, N, C)
    const float* w0   = (const float*)d_in[2];  // (N,)
    const float* s0   = (const float*)d_in[3];  // (N,)
    const float* mask = (const float*)d_in[4];  // (1, N, N)
    const float* df   = (const float*)d_in[5];  // (2C, 1)
    const float* rf   = (const float*)d_in[6];  // (2C, 1)
    float* out = (float*)d_out;

    dim3 grid(GX, GY);   // 8 x 128 = 1024 blocks, single wave at 7 blocks/SM
    fused_kernel<<<grid, NT>>>(X, embs, w0, s0, mask, df, rf, out);
}

// round 6
// speedup vs baseline: 1.1807x; 1.1807x over previous
#include <cuda_runtime.h>
#include <math.h>

#define NN   2048
#define CC   64
#define NT   256            // threads per block
#define JPT  2              // j's per thread
#define JB   (NT * JPT)     // 512 j columns per block
#define GX   (NN / JB)      // 4
#define ICH  16             // i rows per block
#define GY   (NN / ICH)     // 128
#define NBLK (GX * GY)      // 512
#define NBUCK 64
#define L2E  1.4426950408889634f

// ---- device scratch (zero-init at load; counters reset by last block) ----
__device__ float4   g_pos[NN];    // x, y, z, s0
__device__ float4   g_jexp[NN];   // exp(-r_lo), exp(-d_lo), w0, 0   (j-side)
__device__ float4   g_iexp[NN];   // exp(-r_hi), exp(-d_hi), w0, 0   (i-side)
__device__ double   g_accs[NBUCK];
__device__ unsigned g_count;

__device__ __forceinline__ float sqrt_approx(float x) {
    float r; asm("sqrt.approx.f32 %0, %1;" : "=f"(r) : "f"(x)); return r;
}
__device__ __forceinline__ float rcp_approx(float x) {
    float r; asm("rcp.approx.f32 %0, %1;" : "=f"(r) : "f"(x)); return r;
}
__device__ __forceinline__ float ex2_approx(float x) {
    float r; asm("ex2.approx.f32 %0, %1;" : "=f"(r) : "f"(x)); return r;
}

// ---- per-node precompute, warp-cooperative: 1 warp per node ----
__global__ void __launch_bounds__(256) pre_kernel(
    const float* __restrict__ X,
    const float* __restrict__ embs,
    const float* __restrict__ w0,
    const float* __restrict__ s0,
    const float* __restrict__ df,
    const float* __restrict__ rf)
{
    const int lane = threadIdx.x & 31;
    const int n    = (blockIdx.x * 256 + threadIdx.x) >> 5;   // 2048 warps -> 2048 nodes

    const float e0 = embs[(size_t)n * CC + lane];
    const float e1 = embs[(size_t)n * CC + 32 + lane];

    float rl = fmaf(e0, __ldg(rf + lane),      e1 * __ldg(rf + 32 + lane));
    float rh = fmaf(e0, __ldg(rf + 64 + lane), e1 * __ldg(rf + 96 + lane));
    float dl = fmaf(e0, __ldg(df + lane),      e1 * __ldg(df + 32 + lane));
    float dh = fmaf(e0, __ldg(df + 64 + lane), e1 * __ldg(df + 96 + lane));
#pragma unroll
    for (int off = 16; off > 0; off >>= 1) {
        rl += __shfl_xor_sync(0xFFFFFFFFu, rl, off);
        rh += __shfl_xor_sync(0xFFFFFFFFu, rh, off);
        dl += __shfl_xor_sync(0xFFFFFFFFu, dl, off);
        dh += __shfl_xor_sync(0xFFFFFFFFu, dh, off);
    }
    if (lane == 0) {
        const float w = w0[n];
        g_pos[n]  = make_float4(X[3*n], X[3*n+1], X[3*n+2], s0[n]);
        g_jexp[n] = make_float4(ex2_approx(-L2E * rl), ex2_approx(-L2E * dl), w, 0.f);
        g_iexp[n] = make_float4(ex2_approx(-L2E * rh), ex2_approx(-L2E * dh), w, 0.f);
    }
}

// ---- pairwise energy: 2 j's per thread, 16 i's per block ----
__global__ void __launch_bounds__(NT, 4) pair_kernel(
    const float* __restrict__ mask, float* __restrict__ out)
{
    const int tid = threadIdx.x;
    const int j0  = blockIdx.x * JB + tid * JPT;   // consecutive pair (j0, j0+1)
    const int i0  = blockIdx.y * ICH;

    __shared__ float4 sPosI[ICH];   // x, y, z, s0
    __shared__ float4 sMiscI[ICH];  // exp(-r_hi), exp(-d_hi), w0, 0
    __shared__ float  sred[NT];

    // prefetch ALL mask values for this thread (MLP = 16)
    float2 mk[ICH];
#pragma unroll
    for (int k = 0; k < ICH; k++)
        mk[k] = __ldg((const float2*)(mask + (size_t)(i0 + k) * NN + j0));

    // stage i-side node data into shared
    if (tid < ICH)                       sPosI[tid]       = g_pos[i0 + tid];
    else if (tid >= 32 && tid < 32+ICH)  sMiscI[tid - 32] = g_iexp[i0 + (tid - 32)];

    // j-side node data (2 nodes)
    const float4 pjA = g_pos[j0],      pjB = g_pos[j0 + 1];
    const float4 ejA = g_jexp[j0],     ejB = g_jexp[j0 + 1];
    __syncthreads();

    float accA = 0.f, accB = 0.f;
#pragma unroll
    for (int k = 0; k < ICH; k++) {
        const float4 pi = sPosI[k];
        const float4 mi = sMiscI[k];   // eRhi, eDhi, w0i

        // ---------- pair A ----------
        {
            const float dx = pjA.x - pi.x;
            const float dy = pjA.y - pi.y;
            const float dz = pjA.z - pi.z;
            const float r2 = fmaf(dx, dx, fmaf(dy, dy, fmaf(dz, dz, 3e-6f)));
            const float D  = sqrt_approx(r2);

            const float sr = rcp_approx(fmaf(mi.x, ejA.x, 1.f));
            const float sd = rcp_approx(fmaf(mi.y, ejA.y, 1.f));

            const float s  = (pi.w + pjA.w) * fmaf(0.8f, sr, 0.4f);
            const float Dm = D - s;

            const float t   = ex2_approx(-L2E * Dm * Dm);
            const float u   = ex2_approx(fmaf(0.6f * L2E, Dm, -0.09f * L2E));
            const float t2  = t * t;
            const float t3  = t2 * t;
            const float t4  = t2 * t2;
            const float t10 = t4 * t4 * t2;
            const float attr3 = fmaf(t, u, t3 + t10);

            // (sd + 0.5)/3 in one fma
            const float sd3 = fmaf(sd, (1.f/3.f), (1.f/6.f));
            const float w   = sqrt_approx(fmaf(mi.z, ejA.z, 1e-6f)) * sd3;

            const float repl = 5.f * ex2_approx((-0.3f * L2E) * D * r2);
            accA = fmaf(mk[k].x, fmaf(-w, attr3, repl), accA);
        }
        // ---------- pair B ----------
        {
            const float dx = pjB.x - pi.x;
            const float dy = pjB.y - pi.y;
            const float dz = pjB.z - pi.z;
            const float r2 = fmaf(dx, dx, fmaf(dy, dy, fmaf(dz, dz, 3e-6f)));
            const float D  = sqrt_approx(r2);

            const float sr = rcp_approx(fmaf(mi.x, ejB.x, 1.f));
            const float sd = rcp_approx(fmaf(mi.y, ejB.y, 1.f));

            const float s  = (pi.w + pjB.w) * fmaf(0.8f, sr, 0.4f);
            const float Dm = D - s;

            const float t   = ex2_approx(-L2E * Dm * Dm);
            const float u   = ex2_approx(fmaf(0.6f * L2E, Dm, -0.09f * L2E));
            const float t2  = t * t;
            const float t3  = t2 * t;
            const float t4  = t2 * t2;
            const float t10 = t4 * t4 * t2;
            const float attr3 = fmaf(t, u, t3 + t10);

            const float sd3 = fmaf(sd, (1.f/3.f), (1.f/6.f));
            const float w   = sqrt_approx(fmaf(mi.z, ejB.z, 1e-6f)) * sd3;

            const float repl = 5.f * ex2_approx((-0.3f * L2E) * D * r2);
            accB = fmaf(mk[k].y, fmaf(-w, attr3, repl), accB);
        }
    }
    float acc = accA + accB;

    // ---- block reduction ----
    sred[tid] = acc;
    __syncthreads();
#pragma unroll
    for (int off = NT / 2; off >= 32; off >>= 1) {
        if (tid < off) sred[tid] += sred[tid + off];
        __syncthreads();
    }
    if (tid < 32) {
        float v = sred[tid];
#pragma unroll
        for (int off = 16; off > 0; off >>= 1)
            v += __shfl_down_sync(0xFFFFFFFFu, v, off);

        if (tid == 0) {
            const int bucket = (blockIdx.y * GX + blockIdx.x) & (NBUCK - 1);
            atomicAdd(&g_accs[bucket], (double)v);
            __threadfence();
            const unsigned prev = atomicAdd(&g_count, 1u);
            if (prev == NBLK - 1) {
                __threadfence();
                double total = 0.0;
#pragma unroll
                for (int b = 0; b < NBUCK; b++) {
                    total += g_accs[b];
                    g_accs[b] = 0.0;     // reset for next graph replay
                }
                const float r = (float)total;
                out[0] = isnan(r) ? 1e-6f : r;
                g_count = 0u;
            }
        }
    }
}

extern "C" void kernel_launch(void* const* d_in, const int* in_sizes, int n_in,
                              void* d_out, int out_size) {
    const float* X    = (const float*)d_in[0];  // (1, N, 3)
    const float* embs = (const float*)d_in[1];  // (1, N, C)
    const float* w0   = (const float*)d_in[2];  // (N,)
    const float* s0   = (const float*)d_in[3];  // (N,)
    const float* mask = (const float*)d_in[4];  // (1, N, N)
    const float* df   = (const float*)d_in[5];  // (2C, 1)
    const float* rf   = (const float*)d_in[6];  // (2C, 1)
    float* out = (float*)d_out;

    pre_kernel<<<NN / 8, 256>>>(X, embs, w0, s0, df, rf);   // 256 blocks, warp/node
    dim3 grid(GX, GY);   // 4 x 128 = 512 blocks, single wave at 4 blocks/SM
    pair_kernel<<<grid, NT>>>(mask, out);
}

// round 7
// speedup vs baseline: 1.1969x; 1.0137x over previous
#include <cuda_runtime.h>
#include <math.h>

#define NN   2048
#define CC   64
#define NT   256           // threads per block = j columns per block
#define ICH  16            // i rows per block
#define GX   (NN / NT)     // 8
#define GY   (NN / ICH)    // 128
#define NBLK (GX * GY)     // 1024
#define NBUCK 64
#define L2E  1.4426950408889634f

// ---- device scratch (zero-init at load; counters reset by last block) ----
__device__ float4   g_pos[NN];    // x, y, z, s0
__device__ float4   g_jexp[NN];   // exp(-r_lo), exp(-d_lo), w0, 0   (j-side)
__device__ float4   g_iexp[NN];   // exp(-r_hi), exp(-d_hi), w0, 0   (i-side)
__device__ double   g_accs[NBUCK];
__device__ unsigned g_count;

__device__ __forceinline__ float sqrt_approx(float x) {
    float r; asm("sqrt.approx.f32 %0, %1;" : "=f"(r) : "f"(x)); return r;
}
__device__ __forceinline__ float rcp_approx(float x) {
    float r; asm("rcp.approx.f32 %0, %1;" : "=f"(r) : "f"(x)); return r;
}
__device__ __forceinline__ float ex2_approx(float x) {
    float r; asm("ex2.approx.f32 %0, %1;" : "=f"(r) : "f"(x)); return r;
}

// ---- per-node precompute, warp-cooperative: 1 warp per node ----
__global__ void __launch_bounds__(256) pre_kernel(
    const float* __restrict__ X,
    const float* __restrict__ embs,
    const float* __restrict__ w0,
    const float* __restrict__ s0,
    const float* __restrict__ df,
    const float* __restrict__ rf)
{
    const int lane = threadIdx.x & 31;
    const int n    = (blockIdx.x * 256 + threadIdx.x) >> 5;   // 2048 warps -> nodes

    const float e0 = embs[(size_t)n * CC + lane];
    const float e1 = embs[(size_t)n * CC + 32 + lane];

    float rl = fmaf(e0, __ldg(rf + lane),      e1 * __ldg(rf + 32 + lane));
    float rh = fmaf(e0, __ldg(rf + 64 + lane), e1 * __ldg(rf + 96 + lane));
    float dl = fmaf(e0, __ldg(df + lane),      e1 * __ldg(df + 32 + lane));
    float dh = fmaf(e0, __ldg(df + 64 + lane), e1 * __ldg(df + 96 + lane));
#pragma unroll
    for (int off = 16; off > 0; off >>= 1) {
        rl += __shfl_xor_sync(0xFFFFFFFFu, rl, off);
        rh += __shfl_xor_sync(0xFFFFFFFFu, rh, off);
        dl += __shfl_xor_sync(0xFFFFFFFFu, dl, off);
        dh += __shfl_xor_sync(0xFFFFFFFFu, dh, off);
    }
    if (lane == 0) {
        const float w = w0[n];
        g_pos[n]  = make_float4(X[3*n], X[3*n+1], X[3*n+2], s0[n]);
        g_jexp[n] = make_float4(ex2_approx(-L2E * rl), ex2_approx(-L2E * dl), w, 0.f);
        g_iexp[n] = make_float4(ex2_approx(-L2E * rh), ex2_approx(-L2E * dh), w, 0.f);
    }
}

// ---- pairwise energy: 1 j per thread, 16 i's per block, 7 blocks/SM ----
__global__ void __launch_bounds__(NT, 7) pair_kernel(
    const float* __restrict__ mask, float* __restrict__ out)
{
    const int tid  = threadIdx.x;
    const int lane = tid & 31;
    const int wid  = tid >> 5;
    const int j    = blockIdx.x * NT + tid;
    const int i0   = blockIdx.y * ICH;

    __shared__ float4 sPosI[ICH];   // x, y, z, s0
    __shared__ float4 sMiscI[ICH];  // exp(-r_hi), exp(-d_hi), w0, 0

    // prefetch first group of 8 mask values (coalesced; warps hide the rest)
    float mk[8];
#pragma unroll
    for (int k = 0; k < 8; k++)
        mk[k] = __ldg(mask + (size_t)(i0 + k) * NN + j);

    // stage i-side node data into shared
    if (tid < ICH)                        sPosI[tid]       = g_pos[i0 + tid];
    else if (tid >= 32 && tid < 32 + ICH) sMiscI[tid - 32] = g_iexp[i0 + (tid - 32)];

    // j-side node data
    const float4 pj = g_pos[j];    // xj, yj, zj, s0j
    const float4 ej = g_jexp[j];   // eRlo, eDlo, w0j, -
    __syncthreads();

    float acc = 0.f;
#pragma unroll
    for (int g = 0; g < ICH / 8; g++) {
#pragma unroll
        for (int k = 0; k < 8; k++) {
            const int kk = g * 8 + k;
            const float4 pi = sPosI[kk];
            const float4 mi = sMiscI[kk];   // eRhi, eDhi, w0i

            const float dx = pj.x - pi.x;
            const float dy = pj.y - pi.y;
            const float dz = pj.z - pi.z;
            const float r2 = fmaf(dx, dx, fmaf(dy, dy, fmaf(dz, dz, 3e-6f)));
            const float D  = sqrt_approx(r2);

            // sigmoid(a_i + b_j) = 1 / (1 + exp(-a_i) * exp(-b_j))
            const float sr = rcp_approx(fmaf(mi.x, ej.x, 1.f));
            const float sd = rcp_approx(fmaf(mi.y, ej.y, 1.f));

            const float s  = (pi.w + pj.w) * fmaf(0.8f, sr, 0.4f);
            const float Dm = D - s;

            // attr*3 = t*u + t^3 + t^10,  t = exp(-Dm^2), u = exp(0.6 Dm - 0.09)
            const float t   = ex2_approx(-L2E * Dm * Dm);
            const float u   = ex2_approx(fmaf(0.6f * L2E, Dm, -0.09f * L2E));
            const float t2  = t * t;
            const float t3  = t2 * t;
            const float t4  = t2 * t2;
            const float t10 = t4 * t4 * t2;
            const float attr3 = fmaf(t, u, t3 + t10);

            // w/3 = sqrt(w0i*w0j + 1e-6) * (sd/3 + 1/6)
            const float sd3 = fmaf(sd, (1.f/3.f), (1.f/6.f));
            const float w   = sqrt_approx(fmaf(mi.z, ej.z, 1e-6f)) * sd3;

            // repl = 5 * exp(-0.3 * D^3),  D^3 = D * r2
            const float repl = 5.f * ex2_approx((-0.3f * L2E) * D * r2);

            acc = fmaf(mk[k], fmaf(-w, attr3, repl), acc);
        }
        // load next group (reuse the same registers)
        if (g == 0) {
#pragma unroll
            for (int k = 0; k < 8; k++)
                mk[k] = __ldg(mask + (size_t)(i0 + 8 + k) * NN + j);
        }
    }

    // ---- warp reduction + per-warp bucket atomic ----
#pragma unroll
    for (int off = 16; off > 0; off >>= 1)
        acc += __shfl_down_sync(0xFFFFFFFFu, acc, off);

    if (lane == 0) {
        const int bucket = ((blockIdx.y * GX + blockIdx.x) * 8 + wid) & (NBUCK - 1);
        atomicAdd(&g_accs[bucket], (double)acc);
    }
    __syncthreads();   // all 8 warp atomics of this block issued

    if (tid == 0) {
        __threadfence();
        const unsigned prev = atomicAdd(&g_count, 1u);
        if (prev == NBLK - 1) {
            __threadfence();
            double total = 0.0;
#pragma unroll
            for (int b = 0; b < NBUCK; b++) {
                total += g_accs[b];
                g_accs[b] = 0.0;     // reset for next graph replay
            }
            const float r = (float)total;
            out[0] = isnan(r) ? 1e-6f : r;
            g_count = 0u;
        }
    }
}

extern "C" void kernel_launch(void* const* d_in, const int* in_sizes, int n_in,
                              void* d_out, int out_size) {
    const float* X    = (const float*)d_in[0];  // (1, N, 3)
    const float* embs = (const float*)d_in[1];  // (1, N, C)
    const float* w0   = (const float*)d_in[2];  // (N,)
    const float* s0   = (const float*)d_in[3];  // (N,)
    const float* mask = (const float*)d_in[4];  // (1, N, N)
    const float* df   = (const float*)d_in[5];  // (2C, 1)
    const float* rf   = (const float*)d_in[6];  // (2C, 1)
    float* out = (float*)d_out;

    pre_kernel<<<NN / 8, 256>>>(X, embs, w0, s0, df, rf);   // warp per node
    dim3 grid(GX, GY);   // 8 x 128 = 1024 blocks, single wave at 7 blocks/SM
    pair_kernel<<<grid, NT>>>(mask, out);
}